// round 1
// baseline (speedup 1.0000x reference)
#include <cuda_runtime.h>

#define L 320
#define C 128
#define H 4
#define D 32
#define NPOS (L*L)
#define NPROJ 516   // 384 qkv + 4 pair + 128 gate

typedef unsigned long long ull;

// ---------------- scratch (device globals; no allocations allowed) ----------------
__device__ float g_zn[NPOS*C];        // layernormed z
__device__ float g_q[H*L*L*D];        // [(r*H+h)*L + i]*D + d   (q pre-scaled by 1/sqrt(D))
__device__ float g_k[H*L*L*D];
__device__ float g_v[H*L*L*D];
__device__ float g_pbT[H*L*L];        // [(h*L + j)*L + i] = pair_bias[i,j,h]
__device__ float g_gate[NPOS*C];      // sigmoid gate
__device__ float g_att[NPOS*C];       // gated attention output
__device__ float g_W[C*NPROJ];        // packed projection weights [c][n]

// ---------------- packed f32x2 helpers ----------------
__device__ __forceinline__ ull ffma2(ull a, ull b, ull c){
    ull d; asm("fma.rn.f32x2 %0, %1, %2, %3;" : "=l"(d) : "l"(a), "l"(b), "l"(c)); return d;
}
__device__ __forceinline__ ull fadd2(ull a, ull b){
    ull d; asm("add.rn.f32x2 %0, %1, %2;" : "=l"(d) : "l"(a), "l"(b)); return d;
}
__device__ __forceinline__ ull pack2(float x, float y){
    ull r; asm("mov.b64 %0, {%1, %2};" : "=l"(r) : "f"(x), "f"(y)); return r;
}
__device__ __forceinline__ float2 unpack2(ull v){
    float2 f; asm("mov.b64 {%0, %1}, %2;" : "=f"(f.x), "=f"(f.y) : "l"(v)); return f;
}

// ---------------- kernel 1: layernorm ----------------
__global__ void ln_kernel(const float* __restrict__ z,
                          const float* __restrict__ lng,
                          const float* __restrict__ lnb){
    int p = blockIdx.x;
    int t = threadIdx.x;        // 128 threads, one channel each
    float x = z[p*C + t];
    float s = x, s2 = x*x;
    #pragma unroll
    for (int o = 16; o; o >>= 1){
        s  += __shfl_xor_sync(0xFFFFFFFFu, s,  o);
        s2 += __shfl_xor_sync(0xFFFFFFFFu, s2, o);
    }
    __shared__ float ws[4], ws2[4];
    int w = t >> 5;
    if ((t & 31) == 0){ ws[w] = s; ws2[w] = s2; }
    __syncthreads();
    s  = ws[0] + ws[1] + ws[2] + ws[3];
    s2 = ws2[0] + ws2[1] + ws2[2] + ws2[3];
    float m = s * (1.f/C);
    float v = s2 * (1.f/C) - m*m;
    float r = rsqrtf(v + 1e-5f);
    g_zn[p*C + t] = (x - m) * r * lng[t] + lnb[t];
}

// ---------------- kernel 2: pack projection weights [c][n] ----------------
__global__ void pack_kernel(const float* __restrict__ Wqkv,
                            const float* __restrict__ Wpair,
                            const float* __restrict__ Wgate){
    int idx = blockIdx.x * blockDim.x + threadIdx.x;
    if (idx >= C*NPROJ) return;
    int c = idx / NPROJ, n = idx % NPROJ;
    float v;
    if (n < 384)      v = Wqkv[c*384 + n];
    else if (n < 388) v = Wpair[c*4 + (n-384)];
    else              v = Wgate[c*128 + (n-388)];
    g_W[idx] = v;
}

// ---------------- epilogue router for projection GEMM ----------------
__device__ __forceinline__ void epi_proj(int p, int n, float val,
                                         const float* __restrict__ bgate){
    if (n < 384){
        int part = n >> 7;          // 0=q 1=k 2=v
        int rem  = n & 127;
        int h = rem >> 5, d = rem & 31;
        int r = p / L, i = p - r*L;
        int idx = ((r*H + h)*L + i)*D + d;
        if (part == 0)      g_q[idx] = val * 0.17677669529663687f;  // 1/sqrt(32)
        else if (part == 1) g_k[idx] = val;
        else                g_v[idx] = val;
    } else if (n < 388){
        int h = n - 384;
        int i = p / L, j = p - i*L;
        g_pbT[(h*L + j)*L + i] = val;
    } else if (n < NPROJ){
        int c = n - 388;
        g_gate[p*C + c] = 1.f / (1.f + __expf(-(val + bgate[c])));
    }
}

// ---------------- GEMM: BM=128, BN=64, K=128 (chunks of 32), f32x2 micro-kernel ----------------
// MODE 0: A=g_zn, W=g_W (N=516), epilogue routes q/k/v/pair/gate
// MODE 1: A=g_att, W=Wout (N=128), out = A@W + bout
template<int MODE>
__global__ void __launch_bounds__(256)
gemm_kernel(const float* __restrict__ Wext,
            const float* __restrict__ bias,
            float* __restrict__ out){
    constexpr int NW = (MODE == 0) ? NPROJ : 128;
    const float* __restrict__ A = (MODE == 0) ? g_zn : g_att;
    const float* __restrict__ W = (MODE == 0) ? g_W  : Wext;

    const int n0 = blockIdx.x * 64;
    const int m0 = blockIdx.y * 128;
    __shared__ float As[32][132];   // [k][m], transposed, padded
    __shared__ float Ws[32][68];    // [k][n], padded

    int tid = threadIdx.x;
    int tx = tid & 15;              // n-group: 4 outputs
    int ty = tid >> 4;              // m-group: 8 outputs (4 pairs)

    ull acc[4][4];
    #pragma unroll
    for (int a = 0; a < 4; a++)
        #pragma unroll
        for (int b = 0; b < 4; b++) acc[a][b] = 0ull;

    for (int kc = 0; kc < 128; kc += 32){
        // load A tile (128 m x 32 c), store transposed
        #pragma unroll
        for (int t = tid; t < 1024; t += 256){
            int m = t >> 3, c4 = (t & 7) * 4;
            float4 a = *(const float4*)&A[(m0 + m)*C + kc + c4];
            As[c4+0][m] = a.x; As[c4+1][m] = a.y;
            As[c4+2][m] = a.z; As[c4+3][m] = a.w;
        }
        // load W tile (32 c x 64 n)
        if (MODE == 0 && n0 + 64 > NW){
            #pragma unroll
            for (int t = tid; t < 512; t += 256){
                int c = t >> 4, n4 = (t & 15) * 4;
                #pragma unroll
                for (int u = 0; u < 4; u++){
                    int n = n0 + n4 + u;
                    Ws[c][n4+u] = (n < NW) ? W[(kc + c)*NW + n] : 0.f;
                }
            }
        } else {
            #pragma unroll
            for (int t = tid; t < 512; t += 256){
                int c = t >> 4, n4 = (t & 15) * 4;
                *(float4*)&Ws[c][n4] = *(const float4*)&W[(kc + c)*NW + n0 + n4];
            }
        }
        __syncthreads();

        #pragma unroll 8
        for (int k = 0; k < 32; k++){
            // 8 m values as 4 f32x2 pairs (reinterpret — no packing)
            ulonglong2 a01 = *(const ulonglong2*)&As[k][ty*8];
            ulonglong2 a23 = *(const ulonglong2*)&As[k][ty*8 + 4];
            float4 b = *(const float4*)&Ws[k][tx*4];
            ull bs0 = pack2(b.x, b.x), bs1 = pack2(b.y, b.y);
            ull bs2 = pack2(b.z, b.z), bs3 = pack2(b.w, b.w);
            acc[0][0] = ffma2(a01.x, bs0, acc[0][0]);
            acc[0][1] = ffma2(a01.x, bs1, acc[0][1]);
            acc[0][2] = ffma2(a01.x, bs2, acc[0][2]);
            acc[0][3] = ffma2(a01.x, bs3, acc[0][3]);
            acc[1][0] = ffma2(a01.y, bs0, acc[1][0]);
            acc[1][1] = ffma2(a01.y, bs1, acc[1][1]);
            acc[1][2] = ffma2(a01.y, bs2, acc[1][2]);
            acc[1][3] = ffma2(a01.y, bs3, acc[1][3]);
            acc[2][0] = ffma2(a23.x, bs0, acc[2][0]);
            acc[2][1] = ffma2(a23.x, bs1, acc[2][1]);
            acc[2][2] = ffma2(a23.x, bs2, acc[2][2]);
            acc[2][3] = ffma2(a23.x, bs3, acc[2][3]);
            acc[3][0] = ffma2(a23.y, bs0, acc[3][0]);
            acc[3][1] = ffma2(a23.y, bs1, acc[3][1]);
            acc[3][2] = ffma2(a23.y, bs2, acc[3][2]);
            acc[3][3] = ffma2(a23.y, bs3, acc[3][3]);
        }
        __syncthreads();
    }

    // epilogue: acc[mp][j] holds outputs (m0+ty*8+mp*2 +{0,1}, n0+tx*4+j)
    #pragma unroll
    for (int mp = 0; mp < 4; mp++){
        int m = m0 + ty*8 + mp*2;
        #pragma unroll
        for (int j = 0; j < 4; j++){
            int n = n0 + tx*4 + j;
            float2 v2 = unpack2(acc[mp][j]);
            if (MODE == 0){
                epi_proj(m,   n, v2.x, bias);
                epi_proj(m+1, n, v2.y, bias);
            } else {
                float bb = bias[n];
                out[(m  )*C + n] = v2.x + bb;
                out[(m+1)*C + n] = v2.y + bb;
            }
        }
    }
}

// ---------------- kernel 4: attention per (r,h), 320 threads = one per i ----------------
__global__ void __launch_bounds__(320)
attn_kernel(){
    extern __shared__ float sm[];
    float* Ks = sm;             // [320][32]
    float* Vs = sm + L*D;       // [320][32]

    int r = blockIdx.x, h = blockIdx.y;
    int i = threadIdx.x;
    int base = ((r*H + h)*L)*D;

    // cooperative K/V load (fully coalesced, contiguous 40KB each)
    {
        const float4* kg = (const float4*)&g_k[base];
        const float4* vg = (const float4*)&g_v[base];
        float4* Ks4 = (float4*)Ks;
        float4* Vs4 = (float4*)Vs;
        #pragma unroll
        for (int t = i; t < L*D/4; t += L){ Ks4[t] = kg[t]; Vs4[t] = vg[t]; }
    }
    // Q row i as 16 f32x2 pairs
    ull q2[16];
    {
        const ulonglong2* qg = (const ulonglong2*)&g_q[base + i*D];
        #pragma unroll
        for (int t = 0; t < 8; t++){ ulonglong2 qq = qg[t]; q2[2*t] = qq.x; q2[2*t+1] = qq.y; }
    }
    __syncthreads();

    ull acc[16];
    #pragma unroll
    for (int t = 0; t < 16; t++) acc[t] = 0ull;
    float lsum = 0.f;

    const float* pb = &g_pbT[(h*L)*L + i];   // + j*L per step; coalesced over i

    for (int j = 0; j < L; j++){
        float biasv = __ldg(&pb[j*L]);
        const ulonglong2* kj = (const ulonglong2*)&Ks[j*D];
        ull s2a = 0ull, s2b = 0ull;
        #pragma unroll
        for (int t = 0; t < 8; t++){
            ulonglong2 kk = kj[t];
            s2a = ffma2(q2[2*t],   kk.x, s2a);
            s2b = ffma2(q2[2*t+1], kk.y, s2b);
        }
        float2 sf = unpack2(fadd2(s2a, s2b));
        float s = sf.x + sf.y + biasv;
        s = fminf(s, 60.f);                 // scores are O(1); safety clamp only
        float p = __expf(s);
        lsum += p;
        ull p2 = pack2(p, p);
        const ulonglong2* vj = (const ulonglong2*)&Vs[j*D];
        #pragma unroll
        for (int t = 0; t < 8; t++){
            ulonglong2 vv = vj[t];
            acc[2*t]   = ffma2(p2, vv.x, acc[2*t]);
            acc[2*t+1] = ffma2(p2, vv.y, acc[2*t+1]);
        }
    }

    float inv = 1.f / lsum;
    int p = r*L + i;
    const float4* g4 = (const float4*)&g_gate[p*C + h*D];
    float4* o4 = (float4*)&g_att[p*C + h*D];
    #pragma unroll
    for (int t = 0; t < 8; t++){
        float2 x = unpack2(acc[2*t]);
        float2 y = unpack2(acc[2*t+1]);
        float4 g = g4[t];
        float4 o;
        o.x = x.x * inv * g.x;
        o.y = x.y * inv * g.y;
        o.z = y.x * inv * g.z;
        o.w = y.y * inv * g.w;
        o4[t] = o;
    }
}

// ---------------- launch ----------------
extern "C" void kernel_launch(void* const* d_in, const int* in_sizes, int n_in,
                              void* d_out, int out_size){
    const float* z     = (const float*)d_in[0];
    const float* ln_g  = (const float*)d_in[1];
    const float* ln_b  = (const float*)d_in[2];
    const float* Wqkv  = (const float*)d_in[3];
    const float* Wpair = (const float*)d_in[4];
    const float* Wgate = (const float*)d_in[5];
    const float* bgate = (const float*)d_in[6];
    const float* Wout  = (const float*)d_in[7];
    const float* bout  = (const float*)d_in[8];
    float* out = (float*)d_out;

    static bool attr_set = false;
    if (!attr_set){
        cudaFuncSetAttribute(attn_kernel, cudaFuncAttributeMaxDynamicSharedMemorySize,
                             2*L*D*(int)sizeof(float));
        attr_set = true;
    }

    ln_kernel<<<NPOS, 128>>>(z, ln_g, ln_b);
    pack_kernel<<<(C*NPROJ + 255)/256, 256>>>(Wqkv, Wpair, Wgate);
    gemm_kernel<0><<<dim3((NPROJ + 63)/64, NPOS/128), 256>>>(nullptr, bgate, nullptr);
    attn_kernel<<<dim3(L, H), L, 2*L*D*sizeof(float)>>>();
    gemm_kernel<1><<<dim3(128/64, NPOS/128), 256>>>(Wout, bout, out);
}